// round 13
// baseline (speedup 1.0000x reference)
#include <cuda_runtime.h>
#include <cuda_fp16.h>
#include <cstdint>

// Problem dims
#define BATCH 4096
#define TSTEPS 365
#define FDIM 16
#define MT 32              // batch rows per CTA
#define NCTA (BATCH/MT)    // 128
#define NCHUNK 17          // K=272 / 16
#define NPER 5             // smem-persistent chunks (0..4)
#define NSTR 12            // LDG-streamed chunks (5..16)

// strides (elements)
#define LDHH 280           // h row stride in halves (272 + 8 pad)
#define WBH  72            // persist W chunk row stride in halves (64 + 8 pad)
#define SLOT_H (16*WBH)    // 1152 halves = 2304 B per persist slot
#define WREG_B (NPER*SLOT_H*2)  // 11520 B per warp

// SMEM byte offsets (16B aligned)
#define OFF_HH   0                         // 32 x 280 halves = 17920
#define OFF_BIAS 17920                     // 1024 floats = 4096
#define OFF_WOUT 22016                     // 520 floats -> 2112
#define OFF_SH   24128                     // 16 warps x 11520 = 184320
#define SMEM_BYTES (OFF_SH + 16*WREG_B)    // 208448

// ---------------- device globals (preprocessed weights) ----------------
// g_Waug[k][n']: gate-interleaved (n' = j*4+gate) fp16; rows 256..271 = W_ih^T
__device__ __align__(256) __half g_Waug[272 * 1024];
// g_Wfrag: streamed chunks packed in per-lane mma B-fragment order:
// [cg 16][sc 12][lane 32][32 halves]; lane l (gid=l>>2,tig=l&3), idx=nt2*8+e:
//   kl = 2*tig + (e&1) + ((e&2)?8:0),  nl = nt2*16 + gid + ((e&4)?8:0)
__device__ __align__(256) __half g_Wfrag[16 * NSTR * 32 * 32];
__device__ float g_biasP[1024];

__global__ void prep_kernel(const float* __restrict__ W_ih,
                            const float* __restrict__ W_hh,
                            const float* __restrict__ b_ih,
                            const float* __restrict__ b_hh) {
    int tid = blockIdx.x * blockDim.x + threadIdx.x;
    int stride = gridDim.x * blockDim.x;
    for (int o = tid; o < 272 * 1024; o += stride) {
        int k = o >> 10, np = o & 1023;
        int gate = np & 3, j = np >> 2;
        int n = gate * 256 + j;
        float v = (k < 256) ? W_hh[n * 256 + k] : W_ih[n * 16 + (k - 256)];
        g_Waug[o] = __float2half_rn(v);
    }
    for (int o = tid; o < 16 * NSTR * 32 * 32; o += stride) {
        int idx = o & 31;
        int l   = (o >> 5) & 31;
        int t2  = o >> 10;
        int sc  = t2 % NSTR;
        int cg  = t2 / NSTR;
        int kc  = sc + NPER;
        int gid = l >> 2, tig = l & 3;
        int nt2 = idx >> 3, e = idx & 7;
        int kl = 2 * tig + (e & 1) + ((e & 2) ? 8 : 0);
        int nl = nt2 * 16 + gid + ((e & 4) ? 8 : 0);
        int k  = kc * 16 + kl;
        int np = cg * 64 + nl;
        int gate = np & 3, j = np >> 2;
        int n = gate * 256 + j;
        float v = (k < 256) ? W_hh[n * 256 + k] : W_ih[n * 16 + (k - 256)];
        g_Wfrag[o] = __float2half_rn(v);
    }
    for (int o = tid; o < 1024; o += stride) {
        int gate = o & 3, j = o >> 2;
        int n = gate * 256 + j;
        g_biasP[o] = b_ih[n] + b_hh[n];
    }
}

// ---------------- helpers ----------------
__device__ __forceinline__ void cp_async16(void* smem_dst, const void* gsrc) {
    unsigned saddr = (unsigned)__cvta_generic_to_shared(smem_dst);
    asm volatile("cp.async.cg.shared.global [%0], [%1], 16;\n" :: "r"(saddr), "l"(gsrc));
}
__device__ __forceinline__ void cp_commit() { asm volatile("cp.async.commit_group;\n"); }
__device__ __forceinline__ void cp_wait0()  { asm volatile("cp.async.wait_group 0;\n"); }

__device__ __forceinline__ float tanh_raw(float x) {
    float t; asm("tanh.approx.f32 %0, %1;" : "=f"(t) : "f"(x)); return t;
}
__device__ __forceinline__ float sig_approx(float x) {
    return fmaf(0.5f, tanh_raw(0.5f * x), 0.5f);
}
__device__ __forceinline__ float tanhf_fast(float x) {
    x = fminf(fmaxf(x, -15.f), 15.f);
    float e = __expf(-2.f * x);
    return __fdividef(1.f - e, 1.f + e);
}

__device__ __forceinline__ void ldsm_x4(uint32_t* r, const __half* p) {
    uint32_t a = (uint32_t)__cvta_generic_to_shared(p);
    asm volatile("ldmatrix.sync.aligned.m8n8.x4.shared.b16 {%0,%1,%2,%3}, [%4];"
                 : "=r"(r[0]), "=r"(r[1]), "=r"(r[2]), "=r"(r[3]) : "r"(a));
}
__device__ __forceinline__ void ldsm_x4t(uint32_t* r, const __half* p) {
    uint32_t a = (uint32_t)__cvta_generic_to_shared(p);
    asm volatile("ldmatrix.sync.aligned.m8n8.x4.trans.shared.b16 {%0,%1,%2,%3}, [%4];"
                 : "=r"(r[0]), "=r"(r[1]), "=r"(r[2]), "=r"(r[3]) : "r"(a));
}
__device__ __forceinline__ void mma16816(float* d, const uint32_t* a, const uint32_t* b) {
    asm volatile("mma.sync.aligned.m16n8k16.row.col.f32.f16.f16.f32 "
                 "{%0,%1,%2,%3}, {%4,%5,%6,%7}, {%8,%9}, {%0,%1,%2,%3};"
                 : "+f"(d[0]), "+f"(d[1]), "+f"(d[2]), "+f"(d[3])
                 : "r"(a[0]), "r"(a[1]), "r"(a[2]), "r"(a[3]), "r"(b[0]), "r"(b[1]));
}

// stage one persist 16x64 W chunk into smem (init only)
__device__ __forceinline__ void stage_chunk(__half* wbuf, int kc, int cg, int ln) {
#pragma unroll
    for (int it = 0; it < 4; ++it) {
        int lin = it * 32 + ln;
        int row = lin >> 3;
        int c8  = lin & 7;
        cp_async16(wbuf + row * WBH + c8 * 8,
                   &g_Waug[(size_t)(kc * 16 + row) * 1024 + cg * 64 + c8 * 8]);
    }
}

// B-fragment register load: 4x LDG.128 (64B/lane) from fragment-packed stream
__device__ __forceinline__ void ldB(uint4* B, const __half* p) {
    const uint4* q = (const uint4*)p;
    B[0] = q[0]; B[1] = q[1]; B[2] = q[2]; B[3] = q[3];
}

// K=16 chunk from smem-persist slot: 2 A-ldsm + 4 B-ldsm.trans + 16 HMMA
__device__ __forceinline__ void chunk_smem(float (*acc)[8][4], const __half* h_h,
                                           const __half* cur, int kc,
                                           uint32_t aoff0, uint32_t boff) {
    uint32_t a0[4], a1[4];
    ldsm_x4(a0, h_h + kc * 16 + aoff0);
    ldsm_x4(a1, h_h + kc * 16 + aoff0 + 16 * LDHH);
#pragma unroll
    for (int nt2 = 0; nt2 < 4; ++nt2) {
        uint32_t b[4];
        ldsm_x4t(b, cur + boff + nt2 * 16);
        mma16816(acc[0][nt2 * 2],     a0, b);
        mma16816(acc[0][nt2 * 2 + 1], a0, b + 2);
        mma16816(acc[1][nt2 * 2],     a1, b);
        mma16816(acc[1][nt2 * 2 + 1], a1, b + 2);
    }
}

// K=16 chunk with B already in registers: 2 A-ldsm + 16 HMMA
__device__ __forceinline__ void chunk_reg(float (*acc)[8][4], const __half* h_h,
                                          int kc, uint32_t aoff0, const uint4* B) {
    uint32_t a0[4], a1[4];
    ldsm_x4(a0, h_h + kc * 16 + aoff0);
    ldsm_x4(a1, h_h + kc * 16 + aoff0 + 16 * LDHH);
#pragma unroll
    for (int nt2 = 0; nt2 < 4; ++nt2) {
        const uint32_t* b = (const uint32_t*)&B[nt2];
        mma16816(acc[0][nt2 * 2],     a0, b);
        mma16816(acc[0][nt2 * 2 + 1], a0, b + 2);
        mma16816(acc[1][nt2 * 2],     a1, b);
        mma16816(acc[1][nt2 * 2 + 1], a1, b + 2);
    }
}

// ---------------- main persistent LSTM kernel ----------------
__global__ void __launch_bounds__(512, 1)
lstm_kernel(const float* __restrict__ w,
            const float* __restrict__ W_out,
            const float* __restrict__ b_out,
            float* __restrict__ out) {
    extern __shared__ char smb[];
    __half* h_h    = (__half*)(smb + OFF_HH);   // [32][LDHH]: cols 0..255 = h, 256..271 = x_t
    float*  bias_sm= (float*)(smb + OFF_BIAS);
    float*  wout_sm= (float*)(smb + OFF_WOUT);

    const int tid = threadIdx.x;
    const int cg  = tid >> 5;            // warp = col slice: units [cg*16, +16)
    const int ln  = tid & 31;
    const int q   = ln & 3;
    const int b0  = blockIdx.x * MT;

    __half* persist = (__half*)(smb + OFF_SH + cg * WREG_B);
    // per-lane streamed-fragment base: chunk sc at +sc*1024 halves
    const __half* wlane = g_Wfrag + ((size_t)cg * NSTR * 32 + ln) * 32;

    // init: h=0, x(0), bias, wout, persist chunks
    for (int i = tid; i < MT * LDHH; i += 512) h_h[i] = __float2half_rn(0.f);
    for (int i = tid; i < 1024; i += 512) bias_sm[i] = g_biasP[i];
    for (int i = tid; i < 512; i += 512) wout_sm[i] = W_out[i];
    if (tid < 2) wout_sm[512 + tid] = b_out[tid];
    {
        int r = tid >> 4, f = tid & 15;
        h_h[r * LDHH + 256 + f] =
            __float2half_rn(w[((size_t)(b0 + r) * TSTEPS + 0) * FDIM + f]);
    }
#pragma unroll
    for (int p = 0; p < NPER; ++p) stage_chunk(persist + p * SLOT_H, p, cg, ln);
    cp_commit(); cp_wait0(); __syncwarp();

    // lane constants
    const uint32_t aoff0 = (uint32_t)((ln & 15) * LDHH + (ln >> 4) * 8);
    const uint32_t boff  = (uint32_t)((ln & 15) * WBH  + (ln >> 4) * 8);
    const float m0  = (q & 1) ? 1.0f : 0.5f;
    const float a0c = (q & 1) ? 0.0f : 0.5f;
    const int row_l = (ln >> 2) + ((q & 1) << 3);

    float creg[16];
#pragma unroll
    for (int i = 0; i < 16; i++) creg[i] = 0.f;

    uint4 Ba[4], Bb[4];
    ldB(Ba, wlane);              // prefetch streamed chunk 0 (kc=5)

    for (int t = 0; t < TSTEPS; ++t) {
        __syncthreads();  // B0: h(t) + x(t) visible
        float xnext = 0.f;
        if (t + 1 < TSTEPS)
            xnext = w[((size_t)(b0 + (tid >> 4)) * TSTEPS + t + 1) * FDIM + (tid & 15)];

        float acc[2][8][4];
#pragma unroll
        for (int mt = 0; mt < 2; ++mt)
#pragma unroll
            for (int nt = 0; nt < 8; ++nt)
#pragma unroll
                for (int v = 0; v < 4; ++v) acc[mt][nt][v] = 0.f;

        // persistent chunks 0..4 (smem, ldsm)
#pragma unroll
        for (int p = 0; p < NPER; ++p)
            chunk_smem(acc, h_h, persist + p * SLOT_H, p, aoff0, boff);

        // streamed chunks 5..16: B straight from L2 into registers, dbl-buffered
#pragma unroll
        for (int it = 0; it < 6; ++it) {
            ldB(Bb, wlane + (2 * it + 1) * 1024);
            chunk_reg(acc, h_h, NPER + 2 * it, aoff0, Ba);
            ldB(Ba, wlane + ((2 * it + 2) % NSTR) * 1024);  // it=5 wraps to sc=0 (next step)
            chunk_reg(acc, h_h, NPER + 2 * it + 1, aoff0, Bb);
        }
        __syncthreads();  // B1: all h/x reads done before writes

        // stage x(t+1)
        h_h[(tid >> 4) * LDHH + 256 + (tid & 15)] = __float2half_rn(xnext);

        // register epilogue (shfl gate exchange)
#pragma unroll
        for (int mt = 0; mt < 2; ++mt) {
#pragma unroll
            for (int nt = 0; nt < 8; ++nt) {
                float2 bv = *(const float2*)(bias_sm + cg * 64 + nt * 8 + 2 * q);
                float* d = acc[mt][nt];
                float pA0 = d[0] + bv.x, pA1 = d[1] + bv.y;
                float pB0 = d[2] + bv.x, pB1 = d[3] + bv.y;
                float e0A = fmaf(tanh_raw(pA0 * m0), m0, a0c);
                float e1A = sig_approx(pA1);
                float e0B = fmaf(tanh_raw(pB0 * m0), m0, a0c);
                float e1B = sig_approx(pB1);
                bool odd = (q & 1);
                float sx = odd ? e0A : e0B;
                float sy = odd ? e1A : e1B;
                float rx = __shfl_xor_sync(0xffffffffu, sx, 1);
                float ry = __shfl_xor_sync(0xffffffffu, sy, 1);
                float si = odd ? rx  : e0A;
                float sf = odd ? ry  : e1A;
                float tg = odd ? e0B : rx;
                float so = odd ? e1B : ry;
                const int ci = mt * 8 + nt;
                float c = fmaf(sf, creg[ci], si * tg);
                creg[ci] = c;
                float hn = so * tanhf_fast(c);
                const int row = mt * 16 + row_l;
                const int j   = cg * 16 + nt * 2 + (q >> 1);
                h_h[row * LDHH + j] = __float2half_rn(hn);
                if (t == TSTEPS - 1)
                    out[8192 + (size_t)(b0 + row) * 256 + j] = hn;
            }
        }
    }
    __syncthreads();  // final h (in out[]) visible CTA-wide

    // head: tz0 = ELU(h) @ W_out^T + b_out  (exact fp32)
    if (tid < 64) {
        const int r = tid >> 1, oi = tid & 1;
        const float* hrow = out + 8192 + (size_t)(b0 + r) * 256;
        float s = wout_sm[512 + oi];
#pragma unroll 8
        for (int j = 0; j < 256; ++j) {
            float v = hrow[j];
            float e = (v > 0.f) ? v : (__expf(v) - 1.f);
            s = fmaf(e, wout_sm[oi * 256 + j], s);
        }
        out[(size_t)oi * 4096 + (b0 + r)] = s;
    }
}

// ---------------- launch ----------------
extern "C" void kernel_launch(void* const* d_in, const int* in_sizes, int n_in,
                              void* d_out, int out_size) {
    const float* w     = (const float*)d_in[0];
    const float* W_ih  = (const float*)d_in[1];
    const float* W_hh  = (const float*)d_in[2];
    const float* b_ih  = (const float*)d_in[3];
    const float* b_hh  = (const float*)d_in[4];
    const float* W_out = (const float*)d_in[5];
    const float* b_out = (const float*)d_in[6];
    float* out = (float*)d_out;

    prep_kernel<<<256, 256>>>(W_ih, W_hh, b_ih, b_hh);

    cudaFuncSetAttribute(lstm_kernel, cudaFuncAttributeMaxDynamicSharedMemorySize, SMEM_BYTES);
    lstm_kernel<<<NCTA, 512, SMEM_BYTES>>>(w, W_out, b_out, out);
}

// round 14
// speedup vs baseline: 1.2352x; 1.2352x over previous
#include <cuda_runtime.h>
#include <cuda_fp16.h>
#include <cstdint>

// Problem dims
#define BATCH 4096
#define TSTEPS 365
#define FDIM 16
#define MT 32              // batch rows per CTA
#define NCTA (BATCH/MT)    // 128
#define NCHUNK 17          // K=272 / 16
#define NPER 5             // smem-persistent chunks (0..4)
#define NSTR 12            // LDG-streamed chunks (5..16)

// strides (elements)
#define LDHH 280           // h row stride in halves (272 + 8 pad)
#define WBH  72            // persist W chunk row stride in halves (64 + 8 pad)
#define SLOT_H (16*WBH)    // 1152 halves = 2304 B per persist slot
#define WREG_B (NPER*SLOT_H*2)  // 11520 B per warp

// SMEM byte offsets (16B aligned)
#define OFF_HH   0                         // 32 x 280 halves = 17920
#define OFF_BIAS 17920                     // 1024 floats = 4096
#define OFF_WOUT 22016                     // 520 floats -> 2112
#define OFF_SH   24128                     // 16 warps x 11520 = 184320
#define SMEM_BYTES (OFF_SH + 16*WREG_B)    // 208448

// ---------------- device globals (preprocessed weights) ----------------
// g_Waug[k][n']: gate-interleaved (n' = j*4+gate) fp16; rows 256..271 = W_ih^T
__device__ __align__(256) __half g_Waug[272 * 1024];
// g_Wfrag: streamed chunks in per-lane mma B-fragment order, WARP-COALESCED:
// [cg 16][sc 12][i 4][lane 32][8 halves]  (one LDG.128/lane = 512B contiguous/warp)
// lane l (gid=l>>2,tig=l&3), element e (0..7):
//   kl = 2*tig + (e&1) + ((e&2)?8:0),  nl = i*16 + gid + ((e&4)?8:0)
__device__ __align__(256) __half g_Wfrag[16 * NSTR * 4 * 32 * 8];
__device__ float g_biasP[1024];

__global__ void prep_kernel(const float* __restrict__ W_ih,
                            const float* __restrict__ W_hh,
                            const float* __restrict__ b_ih,
                            const float* __restrict__ b_hh) {
    int tid = blockIdx.x * blockDim.x + threadIdx.x;
    int stride = gridDim.x * blockDim.x;
    for (int o = tid; o < 272 * 1024; o += stride) {
        int k = o >> 10, np = o & 1023;
        int gate = np & 3, j = np >> 2;
        int n = gate * 256 + j;
        float v = (k < 256) ? W_hh[n * 256 + k] : W_ih[n * 16 + (k - 256)];
        g_Waug[o] = __float2half_rn(v);
    }
    for (int o = tid; o < 16 * NSTR * 4 * 32 * 8; o += stride) {
        int e  = o & 7;
        int l  = (o >> 3) & 31;
        int i  = (o >> 8) & 3;
        int t2 = o >> 10;
        int sc = t2 % NSTR;
        int cg = t2 / NSTR;
        int kc = sc + NPER;
        int gid = l >> 2, tig = l & 3;
        int kl = 2 * tig + (e & 1) + ((e & 2) ? 8 : 0);
        int nl = i * 16 + gid + ((e & 4) ? 8 : 0);
        int k  = kc * 16 + kl;
        int np = cg * 64 + nl;
        int gate = np & 3, j = np >> 2;
        int n = gate * 256 + j;
        float v = (k < 256) ? W_hh[n * 256 + k] : W_ih[n * 16 + (k - 256)];
        g_Wfrag[o] = __float2half_rn(v);
    }
    for (int o = tid; o < 1024; o += stride) {
        int gate = o & 3, j = o >> 2;
        int n = gate * 256 + j;
        g_biasP[o] = b_ih[n] + b_hh[n];
    }
}

// ---------------- helpers ----------------
__device__ __forceinline__ void cp_async16(void* smem_dst, const void* gsrc) {
    unsigned saddr = (unsigned)__cvta_generic_to_shared(smem_dst);
    asm volatile("cp.async.cg.shared.global [%0], [%1], 16;\n" :: "r"(saddr), "l"(gsrc));
}
__device__ __forceinline__ void cp_commit() { asm volatile("cp.async.commit_group;\n"); }
__device__ __forceinline__ void cp_wait0()  { asm volatile("cp.async.wait_group 0;\n"); }

__device__ __forceinline__ float tanh_raw(float x) {
    float t; asm("tanh.approx.f32 %0, %1;" : "=f"(t) : "f"(x)); return t;
}
__device__ __forceinline__ float sig_approx(float x) {
    return fmaf(0.5f, tanh_raw(0.5f * x), 0.5f);
}
__device__ __forceinline__ float tanhf_fast(float x) {
    x = fminf(fmaxf(x, -15.f), 15.f);
    float e = __expf(-2.f * x);
    return __fdividef(1.f - e, 1.f + e);
}

__device__ __forceinline__ void ldsm_x4(uint32_t* r, const __half* p) {
    uint32_t a = (uint32_t)__cvta_generic_to_shared(p);
    asm volatile("ldmatrix.sync.aligned.m8n8.x4.shared.b16 {%0,%1,%2,%3}, [%4];"
                 : "=r"(r[0]), "=r"(r[1]), "=r"(r[2]), "=r"(r[3]) : "r"(a));
}
__device__ __forceinline__ void ldsm_x4t(uint32_t* r, const __half* p) {
    uint32_t a = (uint32_t)__cvta_generic_to_shared(p);
    asm volatile("ldmatrix.sync.aligned.m8n8.x4.trans.shared.b16 {%0,%1,%2,%3}, [%4];"
                 : "=r"(r[0]), "=r"(r[1]), "=r"(r[2]), "=r"(r[3]) : "r"(a));
}
__device__ __forceinline__ void mma16816(float* d, const uint32_t* a, const uint32_t* b) {
    asm volatile("mma.sync.aligned.m16n8k16.row.col.f32.f16.f16.f32 "
                 "{%0,%1,%2,%3}, {%4,%5,%6,%7}, {%8,%9}, {%0,%1,%2,%3};"
                 : "+f"(d[0]), "+f"(d[1]), "+f"(d[2]), "+f"(d[3])
                 : "r"(a[0]), "r"(a[1]), "r"(a[2]), "r"(a[3]), "r"(b[0]), "r"(b[1]));
}

// stage one persist 16x64 W chunk into smem (init only)
__device__ __forceinline__ void stage_chunk(__half* wbuf, int kc, int cg, int ln) {
#pragma unroll
    for (int it = 0; it < 4; ++it) {
        int lin = it * 32 + ln;
        int row = lin >> 3;
        int c8  = lin & 7;
        cp_async16(wbuf + row * WBH + c8 * 8,
                   &g_Waug[(size_t)(kc * 16 + row) * 1024 + cg * 64 + c8 * 8]);
    }
}

// B-fragment register load: 4x fully-coalesced LDG.128 (512B/warp each)
__device__ __forceinline__ void ldB(uint4* B, const __half* chunk_base, int ln) {
    const uint4* q = (const uint4*)chunk_base;
#pragma unroll
    for (int i = 0; i < 4; ++i) B[i] = q[i * 32 + ln];
}

// K=16 chunk from smem-persist slot: 2 A-ldsm + 4 B-ldsm.trans + 16 HMMA
__device__ __forceinline__ void chunk_smem(float (*acc)[8][4], const __half* h_h,
                                           const __half* cur, int kc,
                                           uint32_t aoff0, uint32_t boff) {
    uint32_t a0[4], a1[4];
    ldsm_x4(a0, h_h + kc * 16 + aoff0);
    ldsm_x4(a1, h_h + kc * 16 + aoff0 + 16 * LDHH);
#pragma unroll
    for (int nt2 = 0; nt2 < 4; ++nt2) {
        uint32_t b[4];
        ldsm_x4t(b, cur + boff + nt2 * 16);
        mma16816(acc[0][nt2 * 2],     a0, b);
        mma16816(acc[0][nt2 * 2 + 1], a0, b + 2);
        mma16816(acc[1][nt2 * 2],     a1, b);
        mma16816(acc[1][nt2 * 2 + 1], a1, b + 2);
    }
}

// K=16 chunk with B already in registers: 2 A-ldsm + 16 HMMA
__device__ __forceinline__ void chunk_reg(float (*acc)[8][4], const __half* h_h,
                                          int kc, uint32_t aoff0, const uint4* B) {
    uint32_t a0[4], a1[4];
    ldsm_x4(a0, h_h + kc * 16 + aoff0);
    ldsm_x4(a1, h_h + kc * 16 + aoff0 + 16 * LDHH);
#pragma unroll
    for (int nt2 = 0; nt2 < 4; ++nt2) {
        const uint32_t* b = (const uint32_t*)&B[nt2];
        mma16816(acc[0][nt2 * 2],     a0, b);
        mma16816(acc[0][nt2 * 2 + 1], a0, b + 2);
        mma16816(acc[1][nt2 * 2],     a1, b);
        mma16816(acc[1][nt2 * 2 + 1], a1, b + 2);
    }
}

// ---------------- main persistent LSTM kernel ----------------
__global__ void __launch_bounds__(512, 1)
lstm_kernel(const float* __restrict__ w,
            const float* __restrict__ W_out,
            const float* __restrict__ b_out,
            float* __restrict__ out) {
    extern __shared__ char smb[];
    __half* h_h    = (__half*)(smb + OFF_HH);   // [32][LDHH]: cols 0..255 = h, 256..271 = x_t
    float*  bias_sm= (float*)(smb + OFF_BIAS);
    float*  wout_sm= (float*)(smb + OFF_WOUT);

    const int tid = threadIdx.x;
    const int cg  = tid >> 5;            // warp = col slice: units [cg*16, +16)
    const int ln  = tid & 31;
    const int q   = ln & 3;
    const int b0  = blockIdx.x * MT;

    __half* persist = (__half*)(smb + OFF_SH + cg * WREG_B);
    // streamed-fragment base for this warp: chunk sc at +sc*1024 halves
    const __half* wcg = g_Wfrag + (size_t)cg * NSTR * 1024;

    // init: h=0, x(0), bias, wout, persist chunks
    for (int i = tid; i < MT * LDHH; i += 512) h_h[i] = __float2half_rn(0.f);
    for (int i = tid; i < 1024; i += 512) bias_sm[i] = g_biasP[i];
    for (int i = tid; i < 512; i += 512) wout_sm[i] = W_out[i];
    if (tid < 2) wout_sm[512 + tid] = b_out[tid];
    {
        int r = tid >> 4, f = tid & 15;
        h_h[r * LDHH + 256 + f] =
            __float2half_rn(w[((size_t)(b0 + r) * TSTEPS + 0) * FDIM + f]);
    }
#pragma unroll
    for (int p = 0; p < NPER; ++p) stage_chunk(persist + p * SLOT_H, p, cg, ln);
    cp_commit(); cp_wait0(); __syncwarp();

    // lane constants
    const uint32_t aoff0 = (uint32_t)((ln & 15) * LDHH + (ln >> 4) * 8);
    const uint32_t boff  = (uint32_t)((ln & 15) * WBH  + (ln >> 4) * 8);
    const float m0  = (q & 1) ? 1.0f : 0.5f;
    const float a0c = (q & 1) ? 0.0f : 0.5f;
    const int row_l = (ln >> 2) + ((q & 1) << 3);

    float creg[16];
#pragma unroll
    for (int i = 0; i < 16; i++) creg[i] = 0.f;

    uint4 Ba[4], Bb[4];
    ldB(Ba, wcg, ln);            // prefetch streamed chunk sc=0 (kc=5)

    for (int t = 0; t < TSTEPS; ++t) {
        __syncthreads();  // B0: h(t) + x(t) visible
        float xnext = 0.f;
        if (t + 1 < TSTEPS)
            xnext = w[((size_t)(b0 + (tid >> 4)) * TSTEPS + t + 1) * FDIM + (tid & 15)];

        float acc[2][8][4];
#pragma unroll
        for (int mt = 0; mt < 2; ++mt)
#pragma unroll
            for (int nt = 0; nt < 8; ++nt)
#pragma unroll
                for (int v = 0; v < 4; ++v) acc[mt][nt][v] = 0.f;

        // persistent chunks 0..4 (smem, ldsm)
#pragma unroll
        for (int p = 0; p < NPER; ++p)
            chunk_smem(acc, h_h, persist + p * SLOT_H, p, aoff0, boff);

        // streamed chunks 5..16: B from L2 straight into registers, dbl-buffered
#pragma unroll
        for (int it = 0; it < 6; ++it) {
            ldB(Bb, wcg + (2 * it + 1) * 1024, ln);
            chunk_reg(acc, h_h, NPER + 2 * it, aoff0, Ba);
            ldB(Ba, wcg + ((2 * it + 2) % NSTR) * 1024, ln);  // it=5 wraps to sc=0 (next step)
            chunk_reg(acc, h_h, NPER + 2 * it + 1, aoff0, Bb);
        }
        __syncthreads();  // B1: all h/x reads done before writes

        // stage x(t+1)
        h_h[(tid >> 4) * LDHH + 256 + (tid & 15)] = __float2half_rn(xnext);

        // register epilogue (shfl gate exchange)
#pragma unroll
        for (int mt = 0; mt < 2; ++mt) {
#pragma unroll
            for (int nt = 0; nt < 8; ++nt) {
                float2 bv = *(const float2*)(bias_sm + cg * 64 + nt * 8 + 2 * q);
                float* d = acc[mt][nt];
                float pA0 = d[0] + bv.x, pA1 = d[1] + bv.y;
                float pB0 = d[2] + bv.x, pB1 = d[3] + bv.y;
                float e0A = fmaf(tanh_raw(pA0 * m0), m0, a0c);
                float e1A = sig_approx(pA1);
                float e0B = fmaf(tanh_raw(pB0 * m0), m0, a0c);
                float e1B = sig_approx(pB1);
                bool odd = (q & 1);
                float sx = odd ? e0A : e0B;
                float sy = odd ? e1A : e1B;
                float rx = __shfl_xor_sync(0xffffffffu, sx, 1);
                float ry = __shfl_xor_sync(0xffffffffu, sy, 1);
                float si = odd ? rx  : e0A;
                float sf = odd ? ry  : e1A;
                float tg = odd ? e0B : rx;
                float so = odd ? e1B : ry;
                const int ci = mt * 8 + nt;
                float c = fmaf(sf, creg[ci], si * tg);
                creg[ci] = c;
                float hn = so * tanhf_fast(c);
                const int row = mt * 16 + row_l;
                const int j   = cg * 16 + nt * 2 + (q >> 1);
                h_h[row * LDHH + j] = __float2half_rn(hn);
                if (t == TSTEPS - 1)
                    out[8192 + (size_t)(b0 + row) * 256 + j] = hn;
            }
        }
    }
    __syncthreads();  // final h (in out[]) visible CTA-wide

    // head: tz0 = ELU(h) @ W_out^T + b_out  (exact fp32)
    if (tid < 64) {
        const int r = tid >> 1, oi = tid & 1;
        const float* hrow = out + 8192 + (size_t)(b0 + r) * 256;
        float s = wout_sm[512 + oi];
#pragma unroll 8
        for (int j = 0; j < 256; ++j) {
            float v = hrow[j];
            float e = (v > 0.f) ? v : (__expf(v) - 1.f);
            s = fmaf(e, wout_sm[oi * 256 + j], s);
        }
        out[(size_t)oi * 4096 + (b0 + r)] = s;
    }
}

// ---------------- launch ----------------
extern "C" void kernel_launch(void* const* d_in, const int* in_sizes, int n_in,
                              void* d_out, int out_size) {
    const float* w     = (const float*)d_in[0];
    const float* W_ih  = (const float*)d_in[1];
    const float* W_hh  = (const float*)d_in[2];
    const float* b_ih  = (const float*)d_in[3];
    const float* b_hh  = (const float*)d_in[4];
    const float* W_out = (const float*)d_in[5];
    const float* b_out = (const float*)d_in[6];
    float* out = (float*)d_out;

    prep_kernel<<<256, 256>>>(W_ih, W_hh, b_ih, b_hh);

    cudaFuncSetAttribute(lstm_kernel, cudaFuncAttributeMaxDynamicSharedMemorySize, SMEM_BYTES);
    lstm_kernel<<<NCTA, 512, SMEM_BYTES>>>(w, W_out, b_out, out);
}

// round 15
// speedup vs baseline: 1.3790x; 1.1164x over previous
#include <cuda_runtime.h>
#include <cuda_fp16.h>
#include <cstdint>

// Problem dims
#define BATCH 4096
#define TSTEPS 365
#define FDIM 16
#define MT 32              // batch rows per CTA
#define NCTA (BATCH/MT)    // 128
#define NCHUNK 17          // K=272 / 16
#define NPER 5             // smem-persistent chunks (0..4)
#define NSTR 12            // LDG-streamed chunks (5..16)

// strides (elements)
#define LDHH 280           // h row stride in halves (272 + 8 pad)
#define WBH  72            // persist W chunk row stride in halves (64 + 8 pad)
#define SLOT_H (16*WBH)    // 1152 halves = 2304 B per persist slot
#define WREG_B (NPER*SLOT_H*2)  // 11520 B per warp

// SMEM byte offsets (16B aligned)
#define HBUF_B   17920                     // one h buffer: 32 x 280 halves
#define OFF_HH   0                         // h buffers x2 = 35840
#define OFF_BIAS 35840                     // 1024 floats = 4096
#define OFF_WOUT 39936                     // 520 floats -> 2112
#define OFF_SH   42048                     // 16 warps x 11520 = 184320
#define SMEM_BYTES (OFF_SH + 16*WREG_B)    // 226368 (< 232448 cap)

// ---------------- device globals (preprocessed weights) ----------------
// g_Waug[k][n']: gate-interleaved (n' = j*4+gate) fp16; rows 256..271 = W_ih^T
__device__ __align__(256) __half g_Waug[272 * 1024];
// g_Wfrag: streamed chunks in per-lane mma B-fragment order, WARP-COALESCED:
// [cg 16][sc 12][i 4][lane 32][8 halves]  (one LDG.128/lane = 512B contiguous/warp)
// lane l (gid=l>>2,tig=l&3), element e (0..7):
//   kl = 2*tig + (e&1) + ((e&2)?8:0),  nl = i*16 + gid + ((e&4)?8:0)
__device__ __align__(256) __half g_Wfrag[16 * NSTR * 4 * 32 * 8];
__device__ float g_biasP[1024];

__global__ void prep_kernel(const float* __restrict__ W_ih,
                            const float* __restrict__ W_hh,
                            const float* __restrict__ b_ih,
                            const float* __restrict__ b_hh) {
    int tid = blockIdx.x * blockDim.x + threadIdx.x;
    int stride = gridDim.x * blockDim.x;
    for (int o = tid; o < 272 * 1024; o += stride) {
        int k = o >> 10, np = o & 1023;
        int gate = np & 3, j = np >> 2;
        int n = gate * 256 + j;
        float v = (k < 256) ? W_hh[n * 256 + k] : W_ih[n * 16 + (k - 256)];
        g_Waug[o] = __float2half_rn(v);
    }
    for (int o = tid; o < 16 * NSTR * 4 * 32 * 8; o += stride) {
        int e  = o & 7;
        int l  = (o >> 3) & 31;
        int i  = (o >> 8) & 3;
        int t2 = o >> 10;
        int sc = t2 % NSTR;
        int cg = t2 / NSTR;
        int kc = sc + NPER;
        int gid = l >> 2, tig = l & 3;
        int kl = 2 * tig + (e & 1) + ((e & 2) ? 8 : 0);
        int nl = i * 16 + gid + ((e & 4) ? 8 : 0);
        int k  = kc * 16 + kl;
        int np = cg * 64 + nl;
        int gate = np & 3, j = np >> 2;
        int n = gate * 256 + j;
        float v = (k < 256) ? W_hh[n * 256 + k] : W_ih[n * 16 + (k - 256)];
        g_Wfrag[o] = __float2half_rn(v);
    }
    for (int o = tid; o < 1024; o += stride) {
        int gate = o & 3, j = o >> 2;
        int n = gate * 256 + j;
        g_biasP[o] = b_ih[n] + b_hh[n];
    }
}

// ---------------- helpers ----------------
__device__ __forceinline__ void cp_async16(void* smem_dst, const void* gsrc) {
    unsigned saddr = (unsigned)__cvta_generic_to_shared(smem_dst);
    asm volatile("cp.async.cg.shared.global [%0], [%1], 16;\n" :: "r"(saddr), "l"(gsrc));
}
__device__ __forceinline__ void cp_commit() { asm volatile("cp.async.commit_group;\n"); }
__device__ __forceinline__ void cp_wait0()  { asm volatile("cp.async.wait_group 0;\n"); }

__device__ __forceinline__ float tanh_raw(float x) {
    float t; asm("tanh.approx.f32 %0, %1;" : "=f"(t) : "f"(x)); return t;
}
__device__ __forceinline__ float sig_approx(float x) {
    return fmaf(0.5f, tanh_raw(0.5f * x), 0.5f);
}

__device__ __forceinline__ void ldsm_x4(uint32_t* r, const __half* p) {
    uint32_t a = (uint32_t)__cvta_generic_to_shared(p);
    asm volatile("ldmatrix.sync.aligned.m8n8.x4.shared.b16 {%0,%1,%2,%3}, [%4];"
                 : "=r"(r[0]), "=r"(r[1]), "=r"(r[2]), "=r"(r[3]) : "r"(a));
}
__device__ __forceinline__ void ldsm_x4t(uint32_t* r, const __half* p) {
    uint32_t a = (uint32_t)__cvta_generic_to_shared(p);
    asm volatile("ldmatrix.sync.aligned.m8n8.x4.trans.shared.b16 {%0,%1,%2,%3}, [%4];"
                 : "=r"(r[0]), "=r"(r[1]), "=r"(r[2]), "=r"(r[3]) : "r"(a));
}
__device__ __forceinline__ void mma16816(float* d, const uint32_t* a, const uint32_t* b) {
    asm volatile("mma.sync.aligned.m16n8k16.row.col.f32.f16.f16.f32 "
                 "{%0,%1,%2,%3}, {%4,%5,%6,%7}, {%8,%9}, {%0,%1,%2,%3};"
                 : "+f"(d[0]), "+f"(d[1]), "+f"(d[2]), "+f"(d[3])
                 : "r"(a[0]), "r"(a[1]), "r"(a[2]), "r"(a[3]), "r"(b[0]), "r"(b[1]));
}

// stage one persist 16x64 W chunk into smem (init only)
__device__ __forceinline__ void stage_chunk(__half* wbuf, int kc, int cg, int ln) {
#pragma unroll
    for (int it = 0; it < 4; ++it) {
        int lin = it * 32 + ln;
        int row = lin >> 3;
        int c8  = lin & 7;
        cp_async16(wbuf + row * WBH + c8 * 8,
                   &g_Waug[(size_t)(kc * 16 + row) * 1024 + cg * 64 + c8 * 8]);
    }
}

// B-fragment register load: 4x fully-coalesced LDG.128 (512B/warp each)
__device__ __forceinline__ void ldB(uint4* B, const __half* chunk_base, int ln) {
    const uint4* q = (const uint4*)chunk_base;
#pragma unroll
    for (int i = 0; i < 4; ++i) B[i] = q[i * 32 + ln];
}

// K=16 chunk from smem-persist slot: 2 A-ldsm + 4 B-ldsm.trans + 16 HMMA
__device__ __forceinline__ void chunk_smem(float (*acc)[8][4], const __half* h_h,
                                           const __half* cur, int kc,
                                           uint32_t aoff0, uint32_t boff) {
    uint32_t a0[4], a1[4];
    ldsm_x4(a0, h_h + kc * 16 + aoff0);
    ldsm_x4(a1, h_h + kc * 16 + aoff0 + 16 * LDHH);
#pragma unroll
    for (int nt2 = 0; nt2 < 4; ++nt2) {
        uint32_t b[4];
        ldsm_x4t(b, cur + boff + nt2 * 16);
        mma16816(acc[0][nt2 * 2],     a0, b);
        mma16816(acc[0][nt2 * 2 + 1], a0, b + 2);
        mma16816(acc[1][nt2 * 2],     a1, b);
        mma16816(acc[1][nt2 * 2 + 1], a1, b + 2);
    }
}

// K=16 chunk with B already in registers: 2 A-ldsm + 16 HMMA
__device__ __forceinline__ void chunk_reg(float (*acc)[8][4], const __half* h_h,
                                          int kc, uint32_t aoff0, const uint4* B) {
    uint32_t a0[4], a1[4];
    ldsm_x4(a0, h_h + kc * 16 + aoff0);
    ldsm_x4(a1, h_h + kc * 16 + aoff0 + 16 * LDHH);
#pragma unroll
    for (int nt2 = 0; nt2 < 4; ++nt2) {
        const uint32_t* b = (const uint32_t*)&B[nt2];
        mma16816(acc[0][nt2 * 2],     a0, b);
        mma16816(acc[0][nt2 * 2 + 1], a0, b + 2);
        mma16816(acc[1][nt2 * 2],     a1, b);
        mma16816(acc[1][nt2 * 2 + 1], a1, b + 2);
    }
}

// ---------------- main persistent LSTM kernel ----------------
__global__ void __launch_bounds__(512, 1)
lstm_kernel(const float* __restrict__ w,
            const float* __restrict__ W_out,
            const float* __restrict__ b_out,
            float* __restrict__ out) {
    extern __shared__ char smb[];
    __half* hbuf0  = (__half*)(smb + OFF_HH);   // [32][LDHH]: cols 0..255 = h, 256..271 = x
    __half* hbuf1  = hbuf0 + HBUF_B / 2;        // second buffer (halves offset)
    float*  bias_sm= (float*)(smb + OFF_BIAS);
    float*  wout_sm= (float*)(smb + OFF_WOUT);

    const int tid = threadIdx.x;
    const int cg  = tid >> 5;            // warp = col slice: units [cg*16, +16)
    const int ln  = tid & 31;
    const int q   = ln & 3;
    const int b0  = blockIdx.x * MT;

    __half* persist = (__half*)(smb + OFF_SH + cg * WREG_B);
    const __half* wcg = g_Wfrag + (size_t)cg * NSTR * 1024;

    // init: h=0 (buf0), x(0) into buf0, bias, wout, persist chunks
    for (int i = tid; i < MT * LDHH; i += 512) hbuf0[i] = __float2half_rn(0.f);
    for (int i = tid; i < 1024; i += 512) bias_sm[i] = g_biasP[i];
    for (int i = tid; i < 512; i += 512) wout_sm[i] = W_out[i];
    if (tid < 2) wout_sm[512 + tid] = b_out[tid];
    {
        int r = tid >> 4, f = tid & 15;
        hbuf0[r * LDHH + 256 + f] =
            __float2half_rn(w[((size_t)(b0 + r) * TSTEPS + 0) * FDIM + f]);
    }
#pragma unroll
    for (int p = 0; p < NPER; ++p) stage_chunk(persist + p * SLOT_H, p, cg, ln);
    cp_commit(); cp_wait0(); __syncwarp();

    // lane constants
    const uint32_t aoff0 = (uint32_t)((ln & 15) * LDHH + (ln >> 4) * 8);
    const uint32_t boff  = (uint32_t)((ln & 15) * WBH  + (ln >> 4) * 8);
    const float m0  = (q & 1) ? 1.0f : 0.5f;
    const float a0c = (q & 1) ? 0.0f : 0.5f;
    const int row_l = (ln >> 2) + ((q & 1) << 3);
    const int xr = tid >> 4, xf = tid & 15;

    float creg[16];
#pragma unroll
    for (int i = 0; i < 16; i++) creg[i] = 0.f;

    uint4 Ba[4], Bb[4];
    ldB(Ba, wcg, ln);            // prefetch streamed chunk sc=0 (kc=5)

    for (int t = 0; t < TSTEPS; ++t) {
        __half* hcur = (t & 1) ? hbuf1 : hbuf0;
        __half* hnxt = (t & 1) ? hbuf0 : hbuf1;
        __syncthreads();  // B0 (only barrier): h(t) + x(t) in hcur fully written
        float xnext = 0.f;
        if (t + 1 < TSTEPS)
            xnext = w[((size_t)(b0 + xr) * TSTEPS + t + 1) * FDIM + xf];

        float acc[2][8][4];
#pragma unroll
        for (int mt = 0; mt < 2; ++mt)
#pragma unroll
            for (int nt = 0; nt < 8; ++nt)
#pragma unroll
                for (int v = 0; v < 4; ++v) acc[mt][nt][v] = 0.f;

        // persistent chunks 0..4 (smem, ldsm)
#pragma unroll
        for (int p = 0; p < NPER; ++p)
            chunk_smem(acc, hcur, persist + p * SLOT_H, p, aoff0, boff);

        // streamed chunks 5..16: B from L2 straight into registers, dbl-buffered
#pragma unroll
        for (int it = 0; it < 6; ++it) {
            ldB(Bb, wcg + (2 * it + 1) * 1024, ln);
            chunk_reg(acc, hcur, NPER + 2 * it, aoff0, Ba);
            ldB(Ba, wcg + ((2 * it + 2) % NSTR) * 1024, ln);  // wraps to next step
            chunk_reg(acc, hcur, NPER + 2 * it + 1, aoff0, Bb);
        }

        // stage x(t+1) into next buffer (own slot; readers sync at next B0)
        hnxt[xr * LDHH + 256 + xf] = __float2half_rn(xnext);

        // register epilogue straight after own mma — overlaps other warps' tails
#pragma unroll
        for (int mt = 0; mt < 2; ++mt) {
#pragma unroll
            for (int nt = 0; nt < 8; ++nt) {
                float2 bv = *(const float2*)(bias_sm + cg * 64 + nt * 8 + 2 * q);
                float* d = acc[mt][nt];
                float pA0 = d[0] + bv.x, pA1 = d[1] + bv.y;
                float pB0 = d[2] + bv.x, pB1 = d[3] + bv.y;
                float e0A = fmaf(tanh_raw(pA0 * m0), m0, a0c);
                float e1A = sig_approx(pA1);
                float e0B = fmaf(tanh_raw(pB0 * m0), m0, a0c);
                float e1B = sig_approx(pB1);
                bool odd = (q & 1);
                float sx = odd ? e0A : e0B;
                float sy = odd ? e1A : e1B;
                float rx = __shfl_xor_sync(0xffffffffu, sx, 1);
                float ry = __shfl_xor_sync(0xffffffffu, sy, 1);
                float si = odd ? rx  : e0A;
                float sf = odd ? ry  : e1A;
                float tg = odd ? e0B : rx;
                float so = odd ? e1B : ry;
                const int ci = mt * 8 + nt;
                float c = fmaf(sf, creg[ci], si * tg);
                creg[ci] = c;
                float hn = so * tanh_raw(c);
                const int row = mt * 16 + row_l;
                const int j   = cg * 16 + nt * 2 + (q >> 1);
                hnxt[row * LDHH + j] = __float2half_rn(hn);
                if (t == TSTEPS - 1)
                    out[8192 + (size_t)(b0 + row) * 256 + j] = hn;
            }
        }
    }
    __syncthreads();  // final h (in out[]) visible CTA-wide

    // head: tz0 = ELU(h) @ W_out^T + b_out  (exact fp32)
    if (tid < 64) {
        const int r = tid >> 1, oi = tid & 1;
        const float* hrow = out + 8192 + (size_t)(b0 + r) * 256;
        float s = wout_sm[512 + oi];
#pragma unroll 8
        for (int j = 0; j < 256; ++j) {
            float v = hrow[j];
            float e = (v > 0.f) ? v : (__expf(v) - 1.f);
            s = fmaf(e, wout_sm[oi * 256 + j], s);
        }
        out[(size_t)oi * 4096 + (b0 + r)] = s;
    }
}

// ---------------- launch ----------------
extern "C" void kernel_launch(void* const* d_in, const int* in_sizes, int n_in,
                              void* d_out, int out_size) {
    const float* w     = (const float*)d_in[0];
    const float* W_ih  = (const float*)d_in[1];
    const float* W_hh  = (const float*)d_in[2];
    const float* b_ih  = (const float*)d_in[3];
    const float* b_hh  = (const float*)d_in[4];
    const float* W_out = (const float*)d_in[5];
    const float* b_out = (const float*)d_in[6];
    float* out = (float*)d_out;

    prep_kernel<<<256, 256>>>(W_ih, W_hh, b_ih, b_hh);

    cudaFuncSetAttribute(lstm_kernel, cudaFuncAttributeMaxDynamicSharedMemorySize, SMEM_BYTES);
    lstm_kernel<<<NCTA, 512, SMEM_BYTES>>>(w, W_out, b_out, out);
}

// round 16
// speedup vs baseline: 1.3795x; 1.0003x over previous
#include <cuda_runtime.h>
#include <cuda_fp16.h>
#include <cstdint>

// Problem dims
#define BATCH 4096
#define TSTEPS 365
#define FDIM 16
#define MT 32              // batch rows per CTA
#define NCTA (BATCH/MT)    // 128
#define NCHUNK 17          // K=272 / 16
#define NPER 5             // smem-persistent chunks (0..4)
#define NSTR 12            // LDG-streamed chunks (5..16)

// strides (elements)
#define LDHH 280           // h row stride in halves (272 + 8 pad)
#define WBH  72            // persist W chunk row stride in halves (64 + 8 pad)
#define SLOT_H (16*WBH)    // 1152 halves = 2304 B per persist slot
#define WREG_B (NPER*SLOT_H*2)  // 11520 B per warp

// SMEM byte offsets (16B aligned)
#define HBUF_B   17920                     // one h buffer: 32 x 280 halves
#define OFF_HH   0                         // h buffers x2 = 35840
#define OFF_BIAS 35840                     // 1024 floats = 4096
#define OFF_WOUT 39936                     // 520 floats -> 2112
#define OFF_SH   42048                     // 16 warps x 11520 = 184320
#define SMEM_BYTES (OFF_SH + 16*WREG_B)    // 226368 (< 232448 cap)

// ---------------- device globals (preprocessed weights) ----------------
// g_Waug[k][n']: gate-interleaved (n' = j*4+gate) fp16; rows 256..271 = W_ih^T
__device__ __align__(256) __half g_Waug[272 * 1024];
// g_Wfrag: streamed chunks in per-lane mma B-fragment order, WARP-COALESCED:
// [cg 16][sc 12][i 4][lane 32][8 halves]  (one LDG.128/lane = 512B contiguous/warp)
// lane l (gid=l>>2,tig=l&3), element e (0..7):
//   kl = 2*tig + (e&1) + ((e&2)?8:0),  nl = i*16 + gid + ((e&4)?8:0)
__device__ __align__(256) __half g_Wfrag[16 * NSTR * 4 * 32 * 8];
__device__ float g_biasP[1024];

__global__ void prep_kernel(const float* __restrict__ W_ih,
                            const float* __restrict__ W_hh,
                            const float* __restrict__ b_ih,
                            const float* __restrict__ b_hh) {
    int tid = blockIdx.x * blockDim.x + threadIdx.x;
    int stride = gridDim.x * blockDim.x;
    for (int o = tid; o < 272 * 1024; o += stride) {
        int k = o >> 10, np = o & 1023;
        int gate = np & 3, j = np >> 2;
        int n = gate * 256 + j;
        float v = (k < 256) ? W_hh[n * 256 + k] : W_ih[n * 16 + (k - 256)];
        g_Waug[o] = __float2half_rn(v);
    }
    for (int o = tid; o < 16 * NSTR * 4 * 32 * 8; o += stride) {
        int e  = o & 7;
        int l  = (o >> 3) & 31;
        int i  = (o >> 8) & 3;
        int t2 = o >> 10;
        int sc = t2 % NSTR;
        int cg = t2 / NSTR;
        int kc = sc + NPER;
        int gid = l >> 2, tig = l & 3;
        int kl = 2 * tig + (e & 1) + ((e & 2) ? 8 : 0);
        int nl = i * 16 + gid + ((e & 4) ? 8 : 0);
        int k  = kc * 16 + kl;
        int np = cg * 64 + nl;
        int gate = np & 3, j = np >> 2;
        int n = gate * 256 + j;
        float v = (k < 256) ? W_hh[n * 256 + k] : W_ih[n * 16 + (k - 256)];
        g_Wfrag[o] = __float2half_rn(v);
    }
    for (int o = tid; o < 1024; o += stride) {
        int gate = o & 3, j = o >> 2;
        int n = gate * 256 + j;
        g_biasP[o] = b_ih[n] + b_hh[n];
    }
}

// ---------------- helpers ----------------
__device__ __forceinline__ void cp_async16(void* smem_dst, const void* gsrc) {
    unsigned saddr = (unsigned)__cvta_generic_to_shared(smem_dst);
    asm volatile("cp.async.cg.shared.global [%0], [%1], 16;\n" :: "r"(saddr), "l"(gsrc));
}
__device__ __forceinline__ void cp_commit() { asm volatile("cp.async.commit_group;\n"); }
__device__ __forceinline__ void cp_wait0()  { asm volatile("cp.async.wait_group 0;\n"); }

__device__ __forceinline__ float tanh_raw(float x) {
    float t; asm("tanh.approx.f32 %0, %1;" : "=f"(t) : "f"(x)); return t;
}
__device__ __forceinline__ float sig_approx(float x) {
    return fmaf(0.5f, tanh_raw(0.5f * x), 0.5f);
}

__device__ __forceinline__ void ldsm_x4(uint32_t* r, const __half* p) {
    uint32_t a = (uint32_t)__cvta_generic_to_shared(p);
    asm volatile("ldmatrix.sync.aligned.m8n8.x4.shared.b16 {%0,%1,%2,%3}, [%4];"
                 : "=r"(r[0]), "=r"(r[1]), "=r"(r[2]), "=r"(r[3]) : "r"(a));
}
__device__ __forceinline__ void ldsm_x4t(uint32_t* r, const __half* p) {
    uint32_t a = (uint32_t)__cvta_generic_to_shared(p);
    asm volatile("ldmatrix.sync.aligned.m8n8.x4.trans.shared.b16 {%0,%1,%2,%3}, [%4];"
                 : "=r"(r[0]), "=r"(r[1]), "=r"(r[2]), "=r"(r[3]) : "r"(a));
}
__device__ __forceinline__ void mma16816(float* d, const uint32_t* a, const uint32_t* b) {
    asm volatile("mma.sync.aligned.m16n8k16.row.col.f32.f16.f16.f32 "
                 "{%0,%1,%2,%3}, {%4,%5,%6,%7}, {%8,%9}, {%0,%1,%2,%3};"
                 : "+f"(d[0]), "+f"(d[1]), "+f"(d[2]), "+f"(d[3])
                 : "r"(a[0]), "r"(a[1]), "r"(a[2]), "r"(a[3]), "r"(b[0]), "r"(b[1]));
}

// stage one persist 16x64 W chunk into smem (init only)
__device__ __forceinline__ void stage_chunk(__half* wbuf, int kc, int cg, int ln) {
#pragma unroll
    for (int it = 0; it < 4; ++it) {
        int lin = it * 32 + ln;
        int row = lin >> 3;
        int c8  = lin & 7;
        cp_async16(wbuf + row * WBH + c8 * 8,
                   &g_Waug[(size_t)(kc * 16 + row) * 1024 + cg * 64 + c8 * 8]);
    }
}

// B-fragment register load: 4x fully-coalesced LDG.128 (512B/warp each)
__device__ __forceinline__ void ldB(uint4* B, const __half* chunk_base, int ln) {
    const uint4* q = (const uint4*)chunk_base;
#pragma unroll
    for (int i = 0; i < 4; ++i) B[i] = q[i * 32 + ln];
}

// load both A fragments (a0: rows 0-15, a1: rows 16-31) for chunk kc -> 8 regs
__device__ __forceinline__ void ldsmA(uint32_t* A, const __half* h_h, int kc, uint32_t aoff0) {
    ldsm_x4(A,     h_h + kc * 16 + aoff0);
    ldsm_x4(A + 4, h_h + kc * 16 + aoff0 + 16 * LDHH);
}

// K=16 chunk from smem-persist slot with pre-loaded A: 4 B-ldsm.trans + 16 HMMA
__device__ __forceinline__ void chunk_smem_pre(float (*acc)[8][4], const uint32_t* A,
                                               const __half* cur, uint32_t boff) {
#pragma unroll
    for (int nt2 = 0; nt2 < 4; ++nt2) {
        uint32_t b[4];
        ldsm_x4t(b, cur + boff + nt2 * 16);
        mma16816(acc[0][nt2 * 2],     A,     b);
        mma16816(acc[0][nt2 * 2 + 1], A,     b + 2);
        mma16816(acc[1][nt2 * 2],     A + 4, b);
        mma16816(acc[1][nt2 * 2 + 1], A + 4, b + 2);
    }
}

// K=16 chunk with pre-loaded A and register B: 16 HMMA, zero loads
__device__ __forceinline__ void chunk_reg_pre(float (*acc)[8][4], const uint32_t* A,
                                              const uint4* B) {
#pragma unroll
    for (int nt2 = 0; nt2 < 4; ++nt2) {
        const uint32_t* b = (const uint32_t*)&B[nt2];
        mma16816(acc[0][nt2 * 2],     A,     b);
        mma16816(acc[0][nt2 * 2 + 1], A,     b + 2);
        mma16816(acc[1][nt2 * 2],     A + 4, b);
        mma16816(acc[1][nt2 * 2 + 1], A + 4, b + 2);
    }
}

// ---------------- main persistent LSTM kernel ----------------
__global__ void __launch_bounds__(512, 1)
lstm_kernel(const float* __restrict__ w,
            const float* __restrict__ W_out,
            const float* __restrict__ b_out,
            float* __restrict__ out) {
    extern __shared__ char smb[];
    __half* hbuf0  = (__half*)(smb + OFF_HH);   // [32][LDHH]: cols 0..255 = h, 256..271 = x
    __half* hbuf1  = hbuf0 + HBUF_B / 2;
    float*  bias_sm= (float*)(smb + OFF_BIAS);
    float*  wout_sm= (float*)(smb + OFF_WOUT);

    const int tid = threadIdx.x;
    const int cg  = tid >> 5;            // warp = col slice: units [cg*16, +16)
    const int ln  = tid & 31;
    const int q   = ln & 3;
    const int b0  = blockIdx.x * MT;

    __half* persist = (__half*)(smb + OFF_SH + cg * WREG_B);
    const __half* wcg = g_Wfrag + (size_t)cg * NSTR * 1024;

    // init: h=0 (buf0), x(0) into buf0, bias, wout, persist chunks
    for (int i = tid; i < MT * LDHH; i += 512) hbuf0[i] = __float2half_rn(0.f);
    for (int i = tid; i < 1024; i += 512) bias_sm[i] = g_biasP[i];
    for (int i = tid; i < 512; i += 512) wout_sm[i] = W_out[i];
    if (tid < 2) wout_sm[512 + tid] = b_out[tid];
    {
        int r = tid >> 4, f = tid & 15;
        hbuf0[r * LDHH + 256 + f] =
            __float2half_rn(w[((size_t)(b0 + r) * TSTEPS + 0) * FDIM + f]);
    }
#pragma unroll
    for (int p = 0; p < NPER; ++p) stage_chunk(persist + p * SLOT_H, p, cg, ln);
    cp_commit(); cp_wait0(); __syncwarp();

    // lane constants
    const uint32_t aoff0 = (uint32_t)((ln & 15) * LDHH + (ln >> 4) * 8);
    const uint32_t boff  = (uint32_t)((ln & 15) * WBH  + (ln >> 4) * 8);
    const float m0  = (q & 1) ? 1.0f : 0.5f;
    const float a0c = (q & 1) ? 0.0f : 0.5f;
    const int row_l = (ln >> 2) + ((q & 1) << 3);
    const int xr = tid >> 4, xf = tid & 15;

    float creg[16];
#pragma unroll
    for (int i = 0; i < 16; i++) creg[i] = 0.f;

    uint4 Ba[4], Bb[4];
    ldB(Ba, wcg, ln);            // prefetch streamed chunk sc=0 (kc=5)

    for (int t = 0; t < TSTEPS; ++t) {
        __half* hcur = (t & 1) ? hbuf1 : hbuf0;
        __half* hnxt = (t & 1) ? hbuf0 : hbuf1;
        __syncthreads();  // B0 (only barrier): h(t) + x(t) in hcur fully written
        float xnext = 0.f;
        if (t + 1 < TSTEPS)
            xnext = w[((size_t)(b0 + xr) * TSTEPS + t + 1) * FDIM + xf];

        float acc[2][8][4];
#pragma unroll
        for (int mt = 0; mt < 2; ++mt)
#pragma unroll
            for (int nt = 0; nt < 8; ++nt)
#pragma unroll
                for (int v = 0; v < 4; ++v) acc[mt][nt][v] = 0.f;

        // A double-buffer: prefetch chunk kc+1's A before chunk kc's mmas
        uint32_t Abuf[2][8];
        ldsmA(Abuf[0], hcur, 0, aoff0);

        // persistent chunks 0..4 (smem B, A pipelined)
#pragma unroll
        for (int p = 0; p < NPER; ++p) {
            ldsmA(Abuf[(p + 1) & 1], hcur, p + 1, aoff0);
            chunk_smem_pre(acc, Abuf[p & 1], persist + p * SLOT_H, boff);
        }

        // streamed chunks 5..16: register B (dbl-buffered LDG) + pipelined A
#pragma unroll
        for (int it = 0; it < 6; ++it) {
            const int kc = NPER + 2 * it;
            ldB(Bb, wcg + (2 * it + 1) * 1024, ln);
            ldsmA(Abuf[(kc + 1) & 1], hcur, kc + 1, aoff0);
            chunk_reg_pre(acc, Abuf[kc & 1], Ba);
            if (kc + 2 < NCHUNK)
                ldsmA(Abuf[kc & 1], hcur, kc + 2, aoff0);
            ldB(Ba, wcg + ((2 * it + 2) % NSTR) * 1024, ln);  // wraps to next step
            chunk_reg_pre(acc, Abuf[(kc + 1) & 1], Bb);
        }

        // stage x(t+1) into next buffer (own slot; readers sync at next B0)
        hnxt[xr * LDHH + 256 + xf] = __float2half_rn(xnext);

        // register epilogue straight after own mma — overlaps other warps' tails
#pragma unroll
        for (int mt = 0; mt < 2; ++mt) {
#pragma unroll
            for (int nt = 0; nt < 8; ++nt) {
                float2 bv = *(const float2*)(bias_sm + cg * 64 + nt * 8 + 2 * q);
                float* d = acc[mt][nt];
                float pA0 = d[0] + bv.x, pA1 = d[1] + bv.y;
                float pB0 = d[2] + bv.x, pB1 = d[3] + bv.y;
                float e0A = fmaf(tanh_raw(pA0 * m0), m0, a0c);
                float e1A = sig_approx(pA1);
                float e0B = fmaf(tanh_raw(pB0 * m0), m0, a0c);
                float e1B = sig_approx(pB1);
                bool odd = (q & 1);
                float sx = odd ? e0A : e0B;
                float sy = odd ? e1A : e1B;
                float rx = __shfl_xor_sync(0xffffffffu, sx, 1);
                float ry = __shfl_xor_sync(0xffffffffu, sy, 1);
                float si = odd ? rx  : e0A;
                float sf = odd ? ry  : e1A;
                float tg = odd ? e0B : rx;
                float so = odd ? e1B : ry;
                const int ci = mt * 8 + nt;
                float c = fmaf(sf, creg[ci], si * tg);
                creg[ci] = c;
                float hn = so * tanh_raw(c);
                const int row = mt * 16 + row_l;
                const int j   = cg * 16 + nt * 2 + (q >> 1);
                hnxt[row * LDHH + j] = __float2half_rn(hn);
                if (t == TSTEPS - 1)
                    out[8192 + (size_t)(b0 + row) * 256 + j] = hn;
            }
        }
    }
    __syncthreads();  // final h (in out[]) visible CTA-wide

    // head: tz0 = ELU(h) @ W_out^T + b_out  (exact fp32)
    if (tid < 64) {
        const int r = tid >> 1, oi = tid & 1;
        const float* hrow = out + 8192 + (size_t)(b0 + r) * 256;
        float s = wout_sm[512 + oi];
#pragma unroll 8
        for (int j = 0; j < 256; ++j) {
            float v = hrow[j];
            float e = (v > 0.f) ? v : (__expf(v) - 1.f);
            s = fmaf(e, wout_sm[oi * 256 + j], s);
        }
        out[(size_t)oi * 4096 + (b0 + r)] = s;
    }
}

// ---------------- launch ----------------
extern "C" void kernel_launch(void* const* d_in, const int* in_sizes, int n_in,
                              void* d_out, int out_size) {
    const float* w     = (const float*)d_in[0];
    const float* W_ih  = (const float*)d_in[1];
    const float* W_hh  = (const float*)d_in[2];
    const float* b_ih  = (const float*)d_in[3];
    const float* b_hh  = (const float*)d_in[4];
    const float* W_out = (const float*)d_in[5];
    const float* b_out = (const float*)d_in[6];
    float* out = (float*)d_out;

    prep_kernel<<<256, 256>>>(W_ih, W_hh, b_ih, b_hh);

    cudaFuncSetAttribute(lstm_kernel, cudaFuncAttributeMaxDynamicSharedMemorySize, SMEM_BYTES);
    lstm_kernel<<<NCTA, 512, SMEM_BYTES>>>(w, W_out, b_out, out);
}